// round 5
// baseline (speedup 1.0000x reference)
#include <cuda_runtime.h>
#include <cuda_bf16.h>
#include <cstdint>
#include <math.h>

typedef __nv_bfloat16 bf16;

#define B_ROWS   512
#define T_STEPS  128
#define DIM_IN   256
#define HDIM     1024
#define FOURH    4096

#define BM 64
#define BN 64            // columns per gate per block
#define NTH 256

// smem layout (bytes). Rows are 32 bf16 of data in a 40-bf16 (80B) stride:
// 8 consecutive ldmatrix row addresses at stride 80B hit distinct 16B banks.
#define A_PLANE_B (64 * 80)            // 5120
#define A_BUF_B   (2 * A_PLANE_B)      // hi+lo
#define B_PLANE_B (256 * 80)           // 20480
#define B_BUF_B   (2 * B_PLANE_B)
#define SM_A_OFF(buf) ((buf) * A_BUF_B)
#define SM_B_OFF(buf) (2 * A_BUF_B + (buf) * B_BUF_B)
#define SMEM_BYTES (2 * A_BUF_B + 2 * B_BUF_B)   // 102400

// ---------------- persistent device scratch ----------------
__device__ bf16  g_h1hi[2][B_ROWS * HDIM];
__device__ bf16  g_h1lo[2][B_ROWS * HDIM];
__device__ bf16  g_h2hi[2][B_ROWS * HDIM];
__device__ bf16  g_h2lo[2][B_ROWS * HDIM];
__device__ float g_c1[(size_t)B_ROWS * HDIM];
__device__ float g_c2[(size_t)B_ROWS * HDIM];
__device__ float g_hfinal[(size_t)B_ROWS * HDIM];
__device__ bf16  g_xhi[(size_t)B_ROWS * T_STEPS * DIM_IN];
__device__ bf16  g_xlo[(size_t)B_ROWS * T_STEPS * DIM_IN];
// transposed split weights: row = gate*1024 + n, K-major
__device__ bf16  g_w1hi[(size_t)FOURH * DIM_IN],  g_w1lo[(size_t)FOURH * DIM_IN];
__device__ bf16  g_u1hi[(size_t)FOURH * HDIM],    g_u1lo[(size_t)FOURH * HDIM];
__device__ bf16  g_w2hi[(size_t)FOURH * HDIM],    g_w2lo[(size_t)FOURH * HDIM];
__device__ bf16  g_u2hi[(size_t)FOURH * HDIM],    g_u2lo[(size_t)FOURH * HDIM];

// ---------------- helpers ----------------
__device__ __forceinline__ uint32_t smem_u32(const void* p) {
    uint32_t a;
    asm("{ .reg .u64 t; cvta.to.shared.u64 t, %1; cvt.u32.u64 %0, t; }" : "=r"(a) : "l"(p));
    return a;
}
__device__ __forceinline__ void cp16(uint32_t s, const void* g) {
    asm volatile("cp.async.cg.shared.global [%0], [%1], 16;" :: "r"(s), "l"(g));
}
__device__ __forceinline__ void cp_commit() { asm volatile("cp.async.commit_group;" ::: "memory"); }
__device__ __forceinline__ void cp_wait1()  { asm volatile("cp.async.wait_group 1;" ::: "memory"); }
__device__ __forceinline__ void cp_wait0()  { asm volatile("cp.async.wait_group 0;" ::: "memory"); }
__device__ __forceinline__ void ldmx4(uint32_t* r, uint32_t a) {
    asm volatile("ldmatrix.sync.aligned.m8n8.x4.shared.b16 {%0,%1,%2,%3}, [%4];"
                 : "=r"(r[0]), "=r"(r[1]), "=r"(r[2]), "=r"(r[3]) : "r"(a));
}
__device__ __forceinline__ void ldmx2(uint32_t* r, uint32_t a) {
    asm volatile("ldmatrix.sync.aligned.m8n8.x2.shared.b16 {%0,%1}, [%2];"
                 : "=r"(r[0]), "=r"(r[1]) : "r"(a));
}
__device__ __forceinline__ void mma_bf16(float* d, const uint32_t* a, const uint32_t* b) {
    asm volatile(
        "mma.sync.aligned.m16n8k16.row.col.f32.bf16.bf16.f32 "
        "{%0,%1,%2,%3}, {%4,%5,%6,%7}, {%8,%9}, {%0,%1,%2,%3};"
        : "+f"(d[0]), "+f"(d[1]), "+f"(d[2]), "+f"(d[3])
        : "r"(a[0]), "r"(a[1]), "r"(a[2]), "r"(a[3]), "r"(b[0]), "r"(b[1]));
}
__device__ __forceinline__ float fsig(float x) { return 1.0f / (1.0f + __expf(-x)); }
__device__ __forceinline__ void split_bf16(float x, bf16& hi, bf16& lo) {
    hi = __float2bfloat16(x);
    lo = __float2bfloat16(x - __bfloat162float(hi));
}

// ---------------- prep kernels ----------------
__global__ void split_chars(const float* __restrict__ x,
                            bf16* __restrict__ hi, bf16* __restrict__ lo, int n) {
    int i = blockIdx.x * blockDim.x + threadIdx.x;
    if (i < n) { bf16 h, l; split_bf16(x[i], h, l); hi[i] = h; lo[i] = l; }
}

// W[K][4096] fp32 -> Whi/Wlo[n4][K] bf16 (n4 = gate*1024 + n)
__global__ void transpose_split_w(const float* __restrict__ W,
                                  bf16* __restrict__ Whi, bf16* __restrict__ Wlo, int K) {
    __shared__ float tile[32][33];
    int nb = blockIdx.x * 32, kb = blockIdx.y * 32;
    int x = threadIdx.x, y = threadIdx.y;
    #pragma unroll
    for (int yy = y; yy < 32; yy += 8)
        tile[yy][x] = W[(size_t)(kb + yy) * FOURH + nb + x];
    __syncthreads();
    #pragma unroll
    for (int yy = y; yy < 32; yy += 8) {
        float w = tile[x][yy];
        bf16 h, l; split_bf16(w, h, l);
        size_t o = (size_t)(nb + yy) * K + kb + x;
        Whi[o] = h; Wlo[o] = l;
    }
}

// ---------------- per-layer step arguments ----------------
struct StepArgs {
    const bf16* Xhi; const bf16* Xlo;
    unsigned long long xstride;
    int Kx;
    const bf16* Hhi; const bf16* Hlo;
    const bf16* Whi; const bf16* Wlo;
    const bf16* Uhi; const bf16* Ulo;
    const float* bias;
    float* C;
    bf16* Ohi; bf16* Olo;
    const int* seqlen; float* hfinal;
    int t; int first;
};

// ---------------- fused dual-layer LSTM step (bf16x3 mma.sync) ----------------
// blockIdx.z selects which layer-step this CTA computes (L1 step t+1 || L2 step t).
__global__ __launch_bounds__(NTH, 2)
void lstm_step(const StepArgs a0, const StepArgs a1)
{
    const StepArgs a = (blockIdx.z == 0) ? a0 : a1;

    extern __shared__ char smemc[];
    const uint32_t sb = smem_u32(smemc);
    const int tid  = threadIdx.x;
    const int lane = tid & 31;
    const int warp = tid >> 5;
    const int wm   = warp >> 2;          // 0..1 -> 32-row slab
    const int wn   = warp & 3;           // 0..3 -> 16-col slab
    const int n0   = blockIdx.x * BN;
    const int row0 = blockIdx.y * BM;

    // ldmatrix lane address components
    const int arow  = (lane & 7) + ((lane >> 3) & 1) * 8;
    const int koffA = (lane >> 4) * 8;
    const int laneb = lane & 15;
    const int brow  = laneb & 7;
    const int koffB = ((laneb >> 3) & 1) * 8;

    float acc[4][2][2][4];
    #pragma unroll
    for (int g = 0; g < 4; ++g)
        #pragma unroll
        for (int mt = 0; mt < 2; ++mt)
            #pragma unroll
            for (int nt = 0; nt < 2; ++nt)
                #pragma unroll
                for (int q = 0; q < 4; ++q) acc[g][mt][nt][q] = 0.f;

    const int c0n = a.Kx >> 5;
    const int nch = a.first ? c0n : (c0n + (HDIM >> 5));

    auto load_chunk = [&](int c, int buf) {
        const int seg = (c < c0n) ? 0 : 1;
        const int k0  = ((seg == 0) ? c : (c - c0n)) << 5;
        const bf16* Ah = (seg == 0) ? a.Xhi : a.Hhi;
        const bf16* Al = (seg == 0) ? a.Xlo : a.Hlo;
        const size_t astr = (seg == 0) ? (size_t)a.xstride : (size_t)HDIM;
        const bf16* Bh = (seg == 0) ? a.Whi : a.Uhi;
        const bf16* Bl = (seg == 0) ? a.Wlo : a.Ulo;
        const int   Kb = (seg == 0) ? a.Kx : HDIM;
        // A: 2 planes x 64 rows x 4 cp16  (512 ops)
        #pragma unroll
        for (int j = 0; j < 2; ++j) {
            int u = j * NTH + tid;
            int pl = u >> 8, rem = u & 255, r = rem >> 2, q = rem & 3;
            const bf16* src = (pl ? Al : Ah) + (size_t)(row0 + r) * astr + k0 + q * 8;
            cp16(sb + SM_A_OFF(buf) + pl * A_PLANE_B + r * 80 + q * 16, src);
        }
        // B: 2 planes x 256 rows x 4 cp16 (2048 ops)
        #pragma unroll
        for (int j = 0; j < 8; ++j) {
            int u = j * NTH + tid;
            int pl = u >> 10, rem = u & 1023, r = rem >> 2, q = rem & 3;
            int n4 = ((r >> 6) << 10) + n0 + (r & 63);
            const bf16* src = (pl ? Bl : Bh) + (size_t)n4 * Kb + k0 + q * 8;
            cp16(sb + SM_B_OFF(buf) + pl * B_PLANE_B + r * 80 + q * 16, src);
        }
        cp_commit();
    };

    load_chunk(0, 0);
    if (nch > 1) load_chunk(1, 1);

    for (int i = 0; i < nch; ++i) {
        if (i + 1 < nch) cp_wait1(); else cp_wait0();
        __syncthreads();
        const int buf = i & 1;
        const uint32_t aB = sb + SM_A_OFF(buf);
        const uint32_t bB = sb + SM_B_OFF(buf);

        #pragma unroll
        for (int ks = 0; ks < 2; ++ks) {
            uint32_t ah[2][4], al[2][4];
            #pragma unroll
            for (int mt = 0; mt < 2; ++mt) {
                uint32_t aa = aB + (uint32_t)((wm * 32 + mt * 16 + arow) * 80
                                              + (ks * 16 + koffA) * 2);
                ldmx4(ah[mt], aa);
                ldmx4(al[mt], aa + A_PLANE_B);
            }
            #pragma unroll
            for (int g = 0; g < 4; ++g) {
                #pragma unroll
                for (int nt = 0; nt < 2; ++nt) {
                    uint32_t ba = bB + (uint32_t)((g * 64 + wn * 16 + nt * 8 + brow) * 80
                                                  + (ks * 16 + koffB) * 2);
                    uint32_t bh[2], bl[2];
                    ldmx2(bh, ba);
                    ldmx2(bl, ba + B_PLANE_B);
                    #pragma unroll
                    for (int mt = 0; mt < 2; ++mt) {
                        mma_bf16(acc[g][mt][nt], ah[mt], bh);
                        mma_bf16(acc[g][mt][nt], ah[mt], bl);
                        mma_bf16(acc[g][mt][nt], al[mt], bh);
                    }
                }
            }
        }
        __syncthreads();
        if (i + 2 < nch) load_chunk(i + 2, buf);
    }

    // ---- fused LSTM cell epilogue ----
    #pragma unroll
    for (int mt = 0; mt < 2; ++mt) {
        #pragma unroll
        for (int half = 0; half < 2; ++half) {
            const int r = row0 + wm * 32 + mt * 16 + half * 8 + (lane >> 2);
            const int slen = a.seqlen ? a.seqlen[r] : 0;
            #pragma unroll
            for (int nt = 0; nt < 2; ++nt) {
                const int c = n0 + wn * 16 + nt * 8 + (lane & 3) * 2;
                float2 cold = make_float2(0.f, 0.f);
                if (!a.first)
                    cold = *reinterpret_cast<const float2*>(a.C + (size_t)r * HDIM + c);
                float cn[2], hn[2];
                #pragma unroll
                for (int j = 0; j < 2; ++j) {
                    const int q = half * 2 + j;
                    float zi = acc[0][mt][nt][q] + a.bias[c + j];
                    float zf = acc[1][mt][nt][q] + a.bias[HDIM + c + j];
                    float zg = acc[2][mt][nt][q] + a.bias[2 * HDIM + c + j];
                    float zo = acc[3][mt][nt][q] + a.bias[3 * HDIM + c + j];
                    float ig = fsig(zi), fg = fsig(zf);
                    float gg = tanhf(zg), og = fsig(zo);
                    float co = (j == 0) ? cold.x : cold.y;
                    cn[j] = fmaf(fg, co, ig * gg);
                    hn[j] = og * tanhf(cn[j]);
                }
                *reinterpret_cast<float2*>(a.C + (size_t)r * HDIM + c) = make_float2(cn[0], cn[1]);
                bf16 h0, l0, h1, l1;
                split_bf16(hn[0], h0, l0);
                split_bf16(hn[1], h1, l1);
                *reinterpret_cast<__nv_bfloat162*>(a.Ohi + (size_t)r * HDIM + c) =
                    __nv_bfloat162(h0, h1);
                *reinterpret_cast<__nv_bfloat162*>(a.Olo + (size_t)r * HDIM + c) =
                    __nv_bfloat162(l0, l1);
                if (a.hfinal && slen - 1 == a.t)
                    *reinterpret_cast<float2*>(a.hfinal + (size_t)r * HDIM + c) =
                        make_float2(hn[0], hn[1]);
            }
        }
    }
}

// ---------------- final dense(1024->3) + relu ----------------
__global__ void dense_kernel(const float* __restrict__ hfinal,
                             const float* __restrict__ Wd,
                             const float* __restrict__ bd,
                             float* __restrict__ out)
{
    const int b = blockIdx.x;
    const float* h = hfinal + (size_t)b * HDIM;

    float s0 = 0.f, s1 = 0.f, s2 = 0.f;
    for (int k = threadIdx.x; k < HDIM; k += blockDim.x) {
        float hv = h[k];
        s0 = fmaf(hv, Wd[k * 3 + 0], s0);
        s1 = fmaf(hv, Wd[k * 3 + 1], s1);
        s2 = fmaf(hv, Wd[k * 3 + 2], s2);
    }
    #pragma unroll
    for (int o = 16; o > 0; o >>= 1) {
        s0 += __shfl_down_sync(0xffffffffu, s0, o);
        s1 += __shfl_down_sync(0xffffffffu, s1, o);
        s2 += __shfl_down_sync(0xffffffffu, s2, o);
    }
    __shared__ float red[8][3];
    const int wid = threadIdx.x >> 5, lane = threadIdx.x & 31;
    if (lane == 0) { red[wid][0] = s0; red[wid][1] = s1; red[wid][2] = s2; }
    __syncthreads();
    if (threadIdx.x == 0) {
        float r0 = 0.f, r1 = 0.f, r2 = 0.f;
        const int nw = blockDim.x >> 5;
        for (int w = 0; w < nw; ++w) { r0 += red[w][0]; r1 += red[w][1]; r2 += red[w][2]; }
        out[b * 3 + 0] = fmaxf(r0 + bd[0], 0.f);
        out[b * 3 + 1] = fmaxf(r1 + bd[1], 0.f);
        out[b * 3 + 2] = fmaxf(r2 + bd[2], 0.f);
    }
}

extern "C" void kernel_launch(void* const* d_in, const int* in_sizes, int n_in,
                              void* d_out, int out_size) {
    const float* chars  = (const float*)d_in[0];
    const int*   seqlen = (const int*)  d_in[1];
    const float* W1 = (const float*)d_in[2];
    const float* U1 = (const float*)d_in[3];
    const float* b1 = (const float*)d_in[4];
    const float* W2 = (const float*)d_in[5];
    const float* U2 = (const float*)d_in[6];
    const float* b2 = (const float*)d_in[7];
    const float* Wd = (const float*)d_in[8];
    const float* bd = (const float*)d_in[9];
    float* out = (float*)d_out;

    bf16 *h1hi, *h1lo, *h2hi, *h2lo, *xhi, *xlo;
    bf16 *w1hi, *w1lo, *u1hi, *u1lo, *w2hi, *w2lo, *u2hi, *u2lo;
    float *c1, *c2, *hfin;
    cudaGetSymbolAddress((void**)&h1hi, g_h1hi);
    cudaGetSymbolAddress((void**)&h1lo, g_h1lo);
    cudaGetSymbolAddress((void**)&h2hi, g_h2hi);
    cudaGetSymbolAddress((void**)&h2lo, g_h2lo);
    cudaGetSymbolAddress((void**)&c1,   g_c1);
    cudaGetSymbolAddress((void**)&c2,   g_c2);
    cudaGetSymbolAddress((void**)&hfin, g_hfinal);
    cudaGetSymbolAddress((void**)&xhi,  g_xhi);
    cudaGetSymbolAddress((void**)&xlo,  g_xlo);
    cudaGetSymbolAddress((void**)&w1hi, g_w1hi);
    cudaGetSymbolAddress((void**)&w1lo, g_w1lo);
    cudaGetSymbolAddress((void**)&u1hi, g_u1hi);
    cudaGetSymbolAddress((void**)&u1lo, g_u1lo);
    cudaGetSymbolAddress((void**)&w2hi, g_w2hi);
    cudaGetSymbolAddress((void**)&w2lo, g_w2lo);
    cudaGetSymbolAddress((void**)&u2hi, g_u2hi);
    cudaGetSymbolAddress((void**)&u2lo, g_u2lo);

    cudaFuncSetAttribute(lstm_step,
                         cudaFuncAttributeMaxDynamicSharedMemorySize, SMEM_BYTES);

    // prep: split chars + weights (per replay, deterministic)
    const int nx = B_ROWS * T_STEPS * DIM_IN;
    split_chars<<<(nx + 255) / 256, 256>>>(chars, xhi, xlo, nx);
    const dim3 tb(32, 8);
    transpose_split_w<<<dim3(FOURH / 32, DIM_IN / 32), tb>>>(W1, w1hi, w1lo, DIM_IN);
    transpose_split_w<<<dim3(FOURH / 32, HDIM  / 32), tb>>>(U1, u1hi, u1lo, HDIM);
    transpose_split_w<<<dim3(FOURH / 32, HDIM  / 32), tb>>>(W2, w2hi, w2lo, HDIM);
    transpose_split_w<<<dim3(FOURH / 32, HDIM  / 32), tb>>>(U2, u2hi, u2lo, HDIM);

    const size_t SLOT = (size_t)B_ROWS * HDIM;

    auto mkL1 = [&](int t) {
        StepArgs s;
        const int prev = t & 1, cur = (t + 1) & 1;
        s.Xhi = xhi + (size_t)t * DIM_IN;  s.Xlo = xlo + (size_t)t * DIM_IN;
        s.xstride = (unsigned long long)(T_STEPS * DIM_IN);
        s.Kx = DIM_IN;
        s.Hhi = h1hi + prev * SLOT;  s.Hlo = h1lo + prev * SLOT;
        s.Whi = w1hi; s.Wlo = w1lo; s.Uhi = u1hi; s.Ulo = u1lo;
        s.bias = b1; s.C = c1;
        s.Ohi = h1hi + cur * SLOT;  s.Olo = h1lo + cur * SLOT;
        s.seqlen = nullptr; s.hfinal = nullptr;
        s.t = t; s.first = (t == 0) ? 1 : 0;
        return s;
    };
    auto mkL2 = [&](int t) {
        StepArgs s;
        const int prev = t & 1, cur = (t + 1) & 1;
        s.Xhi = h1hi + cur * SLOT;  s.Xlo = h1lo + cur * SLOT;   // L1 output of step t
        s.xstride = (unsigned long long)HDIM;
        s.Kx = HDIM;
        s.Hhi = h2hi + prev * SLOT;  s.Hlo = h2lo + prev * SLOT;
        s.Whi = w2hi; s.Wlo = w2lo; s.Uhi = u2hi; s.Ulo = u2lo;
        s.bias = b2; s.C = c2;
        s.Ohi = h2hi + cur * SLOT;  s.Olo = h2lo + cur * SLOT;
        s.seqlen = seqlen; s.hfinal = hfin;
        s.t = t; s.first = (t == 0) ? 1 : 0;
        return s;
    };

    const dim3 grid1(HDIM / BN, B_ROWS / BM, 1);   // (16, 8, 1)
    const dim3 grid2(HDIM / BN, B_ROWS / BM, 2);   // (16, 8, 2)

    // launch 0: L1 step 0 alone
    {
        StepArgs s = mkL1(0);
        lstm_step<<<grid1, NTH, SMEM_BYTES>>>(s, s);
    }
    // launches k = 1..127: L1(k) || L2(k-1)
    for (int k = 1; k < T_STEPS; ++k) {
        StepArgs sA = mkL1(k);
        StepArgs sB = mkL2(k - 1);
        lstm_step<<<grid2, NTH, SMEM_BYTES>>>(sA, sB);
    }
    // final: L2 step 127 alone
    {
        StepArgs s = mkL2(T_STEPS - 1);
        lstm_step<<<grid1, NTH, SMEM_BYTES>>>(s, s);
    }
    dense_kernel<<<B_ROWS, 256>>>(hfin, Wd, bd, out);
}

// round 6
// speedup vs baseline: 1.1855x; 1.1855x over previous
#include <cuda_runtime.h>
#include <cuda_bf16.h>
#include <cstdint>
#include <math.h>

typedef __nv_bfloat16 bf16;

#define B_ROWS   512
#define T_STEPS  128
#define DIM_IN   256
#define HDIM     1024
#define FOURH    4096

#define BM 64
#define BN 64            // columns per gate per block
#define NTH 256

// smem layout (bytes). Rows are 32 bf16 of data in a 40-bf16 (80B) stride.
#define A_PLANE_B (64 * 80)            // 5120
#define A_BUF_B   (2 * A_PLANE_B)      // hi+lo
#define B_PLANE_B (256 * 80)           // 20480
#define B_BUF_B   (2 * B_PLANE_B)
#define SM_A_OFF(buf) ((buf) * A_BUF_B)
#define SM_B_OFF(buf) (2 * A_BUF_B + (buf) * B_BUF_B)
#define SMEM_BYTES (2 * A_BUF_B + 2 * B_BUF_B)   // 102400

// ---------------- persistent device scratch (sorted row space) ----------------
__device__ bf16  g_h1hi[2][B_ROWS * HDIM];
__device__ bf16  g_h1lo[2][B_ROWS * HDIM];
__device__ bf16  g_h2hi[2][B_ROWS * HDIM];
__device__ bf16  g_h2lo[2][B_ROWS * HDIM];
__device__ float g_c1[(size_t)B_ROWS * HDIM];
__device__ float g_c2[(size_t)B_ROWS * HDIM];
__device__ float g_hfinal[(size_t)B_ROWS * HDIM];
__device__ bf16  g_xhi[(size_t)B_ROWS * T_STEPS * DIM_IN];
__device__ bf16  g_xlo[(size_t)B_ROWS * T_STEPS * DIM_IN];
__device__ int   g_perm[B_ROWS];
__device__ int   g_slen[B_ROWS];      // seqlen in sorted space
__device__ int   g_nact[T_STEPS];     // #active rows at step t
// transposed split weights: row = gate*1024 + n, K-major
__device__ bf16  g_w1hi[(size_t)FOURH * DIM_IN],  g_w1lo[(size_t)FOURH * DIM_IN];
__device__ bf16  g_u1hi[(size_t)FOURH * HDIM],    g_u1lo[(size_t)FOURH * HDIM];
__device__ bf16  g_w2hi[(size_t)FOURH * HDIM],    g_w2lo[(size_t)FOURH * HDIM];
__device__ bf16  g_u2hi[(size_t)FOURH * HDIM],    g_u2lo[(size_t)FOURH * HDIM];

// ---------------- helpers ----------------
__device__ __forceinline__ uint32_t smem_u32(const void* p) {
    uint32_t a;
    asm("{ .reg .u64 t; cvta.to.shared.u64 t, %1; cvt.u32.u64 %0, t; }" : "=r"(a) : "l"(p));
    return a;
}
__device__ __forceinline__ void cp16(uint32_t s, const void* g) {
    asm volatile("cp.async.cg.shared.global [%0], [%1], 16;" :: "r"(s), "l"(g));
}
__device__ __forceinline__ void cp_commit() { asm volatile("cp.async.commit_group;" ::: "memory"); }
__device__ __forceinline__ void cp_wait1()  { asm volatile("cp.async.wait_group 1;" ::: "memory"); }
__device__ __forceinline__ void cp_wait0()  { asm volatile("cp.async.wait_group 0;" ::: "memory"); }
__device__ __forceinline__ void ldmx4(uint32_t* r, uint32_t a) {
    asm volatile("ldmatrix.sync.aligned.m8n8.x4.shared.b16 {%0,%1,%2,%3}, [%4];"
                 : "=r"(r[0]), "=r"(r[1]), "=r"(r[2]), "=r"(r[3]) : "r"(a));
}
__device__ __forceinline__ void ldmx2(uint32_t* r, uint32_t a) {
    asm volatile("ldmatrix.sync.aligned.m8n8.x2.shared.b16 {%0,%1}, [%2];"
                 : "=r"(r[0]), "=r"(r[1]) : "r"(a));
}
__device__ __forceinline__ void mma_bf16(float* d, const uint32_t* a, const uint32_t* b) {
    asm volatile(
        "mma.sync.aligned.m16n8k16.row.col.f32.bf16.bf16.f32 "
        "{%0,%1,%2,%3}, {%4,%5,%6,%7}, {%8,%9}, {%0,%1,%2,%3};"
        : "+f"(d[0]), "+f"(d[1]), "+f"(d[2]), "+f"(d[3])
        : "r"(a[0]), "r"(a[1]), "r"(a[2]), "r"(a[3]), "r"(b[0]), "r"(b[1]));
}
__device__ __forceinline__ float fsig(float x) { return 1.0f / (1.0f + __expf(-x)); }
__device__ __forceinline__ void split_bf16(float x, bf16& hi, bf16& lo) {
    hi = __float2bfloat16(x);
    lo = __float2bfloat16(x - __bfloat162float(hi));
}

// ---------------- prep kernels ----------------

// Deterministic rank sort by descending seqlen (stable by original index).
// Also computes n_act[t] = #rows with seqlen >= t+1 and sorted seqlen.
__global__ void sort_rows(const int* __restrict__ seqlen,
                          int* __restrict__ perm, int* __restrict__ slen,
                          int* __restrict__ nact) {
    __shared__ int keys[B_ROWS];
    const int i = threadIdx.x;
    keys[i] = seqlen[i];
    __syncthreads();
    const int k = keys[i];
    int rank = 0;
    for (int j = 0; j < B_ROWS; ++j) {
        int kj = keys[j];
        rank += (kj > k) || (kj == k && j < i);
    }
    perm[rank] = i;
    slen[rank] = k;
    if (i < T_STEPS) {
        int cnt = 0;
        for (int j = 0; j < B_ROWS; ++j) cnt += (keys[j] >= i + 1);
        nact[i] = cnt;
    }
}

// Gather chars into sorted row order and split to bf16 hi/lo planes.
__global__ void split_chars_perm(const float* __restrict__ x,
                                 const int* __restrict__ perm,
                                 bf16* __restrict__ hi, bf16* __restrict__ lo) {
    const int n = B_ROWS * T_STEPS * DIM_IN;
    int i = blockIdx.x * blockDim.x + threadIdx.x;
    if (i >= n) return;
    const int row_elems = T_STEPS * DIM_IN;
    int bs = i / row_elems, d = i - bs * row_elems;
    float v = x[(size_t)perm[bs] * row_elems + d];
    bf16 h, l; split_bf16(v, h, l);
    hi[i] = h; lo[i] = l;
}

// W[K][4096] fp32 -> Whi/Wlo[n4][K] bf16 (n4 = gate*1024 + n)
__global__ void transpose_split_w(const float* __restrict__ W,
                                  bf16* __restrict__ Whi, bf16* __restrict__ Wlo, int K) {
    __shared__ float tile[32][33];
    int nb = blockIdx.x * 32, kb = blockIdx.y * 32;
    int x = threadIdx.x, y = threadIdx.y;
    #pragma unroll
    for (int yy = y; yy < 32; yy += 8)
        tile[yy][x] = W[(size_t)(kb + yy) * FOURH + nb + x];
    __syncthreads();
    #pragma unroll
    for (int yy = y; yy < 32; yy += 8) {
        float w = tile[x][yy];
        bf16 h, l; split_bf16(w, h, l);
        size_t o = (size_t)(nb + yy) * K + kb + x;
        Whi[o] = h; Wlo[o] = l;
    }
}

// ---------------- per-layer step arguments ----------------
struct StepArgs {
    const bf16* Xhi; const bf16* Xlo;
    unsigned long long xstride;
    int Kx;
    const bf16* Hhi; const bf16* Hlo;
    const bf16* Whi; const bf16* Wlo;
    const bf16* Uhi; const bf16* Ulo;
    const float* bias;
    float* C;
    bf16* Ohi; bf16* Olo;
    const int* seqlen;      // sorted-space seqlen (L2 only)
    float* hfinal;
    const int* nact;
    int t; int first;
};

// ---------------- fused dual-layer LSTM step (bf16x3 mma.sync) ----------------
__global__ __launch_bounds__(NTH)
void lstm_step(const StepArgs a0, const StepArgs a1)
{
    const StepArgs a = (blockIdx.z == 0) ? a0 : a1;
    const int row0 = blockIdx.y * BM;
    // dead-row early exit: rows >= n_act[t] never influence the output
    if (row0 >= a.nact[a.t]) return;

    extern __shared__ char smemc[];
    const uint32_t sb = smem_u32(smemc);
    const int tid  = threadIdx.x;
    const int lane = tid & 31;
    const int warp = tid >> 5;
    const int wm   = warp >> 2;          // 0..1 -> 32-row slab
    const int wn   = warp & 3;           // 0..3 -> 16-col slab
    const int n0   = blockIdx.x * BN;

    const int arow  = (lane & 7) + ((lane >> 3) & 1) * 8;
    const int koffA = (lane >> 4) * 8;
    const int laneb = lane & 15;
    const int brow  = laneb & 7;
    const int koffB = ((laneb >> 3) & 1) * 8;

    float acc[4][2][2][4];
    #pragma unroll
    for (int g = 0; g < 4; ++g)
        #pragma unroll
        for (int mt = 0; mt < 2; ++mt)
            #pragma unroll
            for (int nt = 0; nt < 2; ++nt)
                #pragma unroll
                for (int q = 0; q < 4; ++q) acc[g][mt][nt][q] = 0.f;

    const int c0n = a.Kx >> 5;
    const int nch = a.first ? c0n : (c0n + (HDIM >> 5));

    auto load_chunk = [&](int c, int buf) {
        const int seg = (c < c0n) ? 0 : 1;
        const int k0  = ((seg == 0) ? c : (c - c0n)) << 5;
        const bf16* Ah = (seg == 0) ? a.Xhi : a.Hhi;
        const bf16* Al = (seg == 0) ? a.Xlo : a.Hlo;
        const size_t astr = (seg == 0) ? (size_t)a.xstride : (size_t)HDIM;
        const bf16* Bh = (seg == 0) ? a.Whi : a.Uhi;
        const bf16* Bl = (seg == 0) ? a.Wlo : a.Ulo;
        const int   Kb = (seg == 0) ? a.Kx : HDIM;
        #pragma unroll
        for (int j = 0; j < 2; ++j) {
            int u = j * NTH + tid;
            int pl = u >> 8, rem = u & 255, r = rem >> 2, q = rem & 3;
            const bf16* src = (pl ? Al : Ah) + (size_t)(row0 + r) * astr + k0 + q * 8;
            cp16(sb + SM_A_OFF(buf) + pl * A_PLANE_B + r * 80 + q * 16, src);
        }
        #pragma unroll
        for (int j = 0; j < 8; ++j) {
            int u = j * NTH + tid;
            int pl = u >> 10, rem = u & 1023, r = rem >> 2, q = rem & 3;
            int n4 = ((r >> 6) << 10) + n0 + (r & 63);
            const bf16* src = (pl ? Bl : Bh) + (size_t)n4 * Kb + k0 + q * 8;
            cp16(sb + SM_B_OFF(buf) + pl * B_PLANE_B + r * 80 + q * 16, src);
        }
        cp_commit();
    };

    load_chunk(0, 0);
    if (nch > 1) load_chunk(1, 1);

    for (int i = 0; i < nch; ++i) {
        if (i + 1 < nch) cp_wait1(); else cp_wait0();
        __syncthreads();
        const int buf = i & 1;
        const uint32_t aB = sb + SM_A_OFF(buf);
        const uint32_t bB = sb + SM_B_OFF(buf);

        #pragma unroll
        for (int ks = 0; ks < 2; ++ks) {
            uint32_t ah[2][4], al[2][4];
            #pragma unroll
            for (int mt = 0; mt < 2; ++mt) {
                uint32_t aa = aB + (uint32_t)((wm * 32 + mt * 16 + arow) * 80
                                              + (ks * 16 + koffA) * 2);
                ldmx4(ah[mt], aa);
                ldmx4(al[mt], aa + A_PLANE_B);
            }
            #pragma unroll
            for (int g = 0; g < 4; ++g) {
                #pragma unroll
                for (int nt = 0; nt < 2; ++nt) {
                    uint32_t ba = bB + (uint32_t)((g * 64 + wn * 16 + nt * 8 + brow) * 80
                                                  + (ks * 16 + koffB) * 2);
                    uint32_t bh[2], bl[2];
                    ldmx2(bh, ba);
                    ldmx2(bl, ba + B_PLANE_B);
                    #pragma unroll
                    for (int mt = 0; mt < 2; ++mt) {
                        mma_bf16(acc[g][mt][nt], ah[mt], bh);
                        mma_bf16(acc[g][mt][nt], ah[mt], bl);
                        mma_bf16(acc[g][mt][nt], al[mt], bh);
                    }
                }
            }
        }
        __syncthreads();
        if (i + 2 < nch) load_chunk(i + 2, buf);
    }

    // ---- fused LSTM cell epilogue ----
    #pragma unroll
    for (int mt = 0; mt < 2; ++mt) {
        #pragma unroll
        for (int half = 0; half < 2; ++half) {
            const int r = row0 + wm * 32 + mt * 16 + half * 8 + (lane >> 2);
            const int slen = a.seqlen ? a.seqlen[r] : 0;
            #pragma unroll
            for (int nt = 0; nt < 2; ++nt) {
                const int c = n0 + wn * 16 + nt * 8 + (lane & 3) * 2;
                float2 cold = make_float2(0.f, 0.f);
                if (!a.first)
                    cold = *reinterpret_cast<const float2*>(a.C + (size_t)r * HDIM + c);
                float cn[2], hn[2];
                #pragma unroll
                for (int j = 0; j < 2; ++j) {
                    const int q = half * 2 + j;
                    float zi = acc[0][mt][nt][q] + a.bias[c + j];
                    float zf = acc[1][mt][nt][q] + a.bias[HDIM + c + j];
                    float zg = acc[2][mt][nt][q] + a.bias[2 * HDIM + c + j];
                    float zo = acc[3][mt][nt][q] + a.bias[3 * HDIM + c + j];
                    float ig = fsig(zi), fg = fsig(zf);
                    float gg = tanhf(zg), og = fsig(zo);
                    float co = (j == 0) ? cold.x : cold.y;
                    cn[j] = fmaf(fg, co, ig * gg);
                    hn[j] = og * tanhf(cn[j]);
                }
                *reinterpret_cast<float2*>(a.C + (size_t)r * HDIM + c) = make_float2(cn[0], cn[1]);
                bf16 h0, l0, h1, l1;
                split_bf16(hn[0], h0, l0);
                split_bf16(hn[1], h1, l1);
                *reinterpret_cast<__nv_bfloat162*>(a.Ohi + (size_t)r * HDIM + c) =
                    __nv_bfloat162(h0, h1);
                *reinterpret_cast<__nv_bfloat162*>(a.Olo + (size_t)r * HDIM + c) =
                    __nv_bfloat162(l0, l1);
                if (a.hfinal && slen - 1 == a.t)
                    *reinterpret_cast<float2*>(a.hfinal + (size_t)r * HDIM + c) =
                        make_float2(hn[0], hn[1]);
            }
        }
    }
}

// ---------------- final dense(1024->3) + relu (sorted -> original order) ----------------
__global__ void dense_kernel(const float* __restrict__ hfinal,
                             const int* __restrict__ perm,
                             const float* __restrict__ Wd,
                             const float* __restrict__ bd,
                             float* __restrict__ out)
{
    const int bs = blockIdx.x;
    const float* h = hfinal + (size_t)bs * HDIM;

    float s0 = 0.f, s1 = 0.f, s2 = 0.f;
    for (int k = threadIdx.x; k < HDIM; k += blockDim.x) {
        float hv = h[k];
        s0 = fmaf(hv, Wd[k * 3 + 0], s0);
        s1 = fmaf(hv, Wd[k * 3 + 1], s1);
        s2 = fmaf(hv, Wd[k * 3 + 2], s2);
    }
    #pragma unroll
    for (int o = 16; o > 0; o >>= 1) {
        s0 += __shfl_down_sync(0xffffffffu, s0, o);
        s1 += __shfl_down_sync(0xffffffffu, s1, o);
        s2 += __shfl_down_sync(0xffffffffu, s2, o);
    }
    __shared__ float red[8][3];
    const int wid = threadIdx.x >> 5, lane = threadIdx.x & 31;
    if (lane == 0) { red[wid][0] = s0; red[wid][1] = s1; red[wid][2] = s2; }
    __syncthreads();
    if (threadIdx.x == 0) {
        float r0 = 0.f, r1 = 0.f, r2 = 0.f;
        const int nw = blockDim.x >> 5;
        for (int w = 0; w < nw; ++w) { r0 += red[w][0]; r1 += red[w][1]; r2 += red[w][2]; }
        const int b = perm[bs];
        out[b * 3 + 0] = fmaxf(r0 + bd[0], 0.f);
        out[b * 3 + 1] = fmaxf(r1 + bd[1], 0.f);
        out[b * 3 + 2] = fmaxf(r2 + bd[2], 0.f);
    }
}

extern "C" void kernel_launch(void* const* d_in, const int* in_sizes, int n_in,
                              void* d_out, int out_size) {
    const float* chars  = (const float*)d_in[0];
    const int*   seqlen = (const int*)  d_in[1];
    const float* W1 = (const float*)d_in[2];
    const float* U1 = (const float*)d_in[3];
    const float* b1 = (const float*)d_in[4];
    const float* W2 = (const float*)d_in[5];
    const float* U2 = (const float*)d_in[6];
    const float* b2 = (const float*)d_in[7];
    const float* Wd = (const float*)d_in[8];
    const float* bd = (const float*)d_in[9];
    float* out = (float*)d_out;

    bf16 *h1hi, *h1lo, *h2hi, *h2lo, *xhi, *xlo;
    bf16 *w1hi, *w1lo, *u1hi, *u1lo, *w2hi, *w2lo, *u2hi, *u2lo;
    float *c1, *c2, *hfin;
    int *perm, *slen, *nact;
    cudaGetSymbolAddress((void**)&h1hi, g_h1hi);
    cudaGetSymbolAddress((void**)&h1lo, g_h1lo);
    cudaGetSymbolAddress((void**)&h2hi, g_h2hi);
    cudaGetSymbolAddress((void**)&h2lo, g_h2lo);
    cudaGetSymbolAddress((void**)&c1,   g_c1);
    cudaGetSymbolAddress((void**)&c2,   g_c2);
    cudaGetSymbolAddress((void**)&hfin, g_hfinal);
    cudaGetSymbolAddress((void**)&xhi,  g_xhi);
    cudaGetSymbolAddress((void**)&xlo,  g_xlo);
    cudaGetSymbolAddress((void**)&perm, g_perm);
    cudaGetSymbolAddress((void**)&slen, g_slen);
    cudaGetSymbolAddress((void**)&nact, g_nact);
    cudaGetSymbolAddress((void**)&w1hi, g_w1hi);
    cudaGetSymbolAddress((void**)&w1lo, g_w1lo);
    cudaGetSymbolAddress((void**)&u1hi, g_u1hi);
    cudaGetSymbolAddress((void**)&u1lo, g_u1lo);
    cudaGetSymbolAddress((void**)&w2hi, g_w2hi);
    cudaGetSymbolAddress((void**)&w2lo, g_w2lo);
    cudaGetSymbolAddress((void**)&u2hi, g_u2hi);
    cudaGetSymbolAddress((void**)&u2lo, g_u2lo);

    cudaFuncSetAttribute(lstm_step,
                         cudaFuncAttributeMaxDynamicSharedMemorySize, SMEM_BYTES);

    // prep: sort rows, permute+split chars, split+transpose weights
    sort_rows<<<1, B_ROWS>>>(seqlen, perm, slen, nact);
    const int nx = B_ROWS * T_STEPS * DIM_IN;
    split_chars_perm<<<(nx + 255) / 256, 256>>>(chars, perm, xhi, xlo);
    const dim3 tb(32, 8);
    transpose_split_w<<<dim3(FOURH / 32, DIM_IN / 32), tb>>>(W1, w1hi, w1lo, DIM_IN);
    transpose_split_w<<<dim3(FOURH / 32, HDIM  / 32), tb>>>(U1, u1hi, u1lo, HDIM);
    transpose_split_w<<<dim3(FOURH / 32, HDIM  / 32), tb>>>(W2, w2hi, w2lo, HDIM);
    transpose_split_w<<<dim3(FOURH / 32, HDIM  / 32), tb>>>(U2, u2hi, u2lo, HDIM);

    const size_t SLOT = (size_t)B_ROWS * HDIM;

    auto mkL1 = [&](int t) {
        StepArgs s;
        const int prev = t & 1, cur = (t + 1) & 1;
        s.Xhi = xhi + (size_t)t * DIM_IN;  s.Xlo = xlo + (size_t)t * DIM_IN;
        s.xstride = (unsigned long long)(T_STEPS * DIM_IN);
        s.Kx = DIM_IN;
        s.Hhi = h1hi + prev * SLOT;  s.Hlo = h1lo + prev * SLOT;
        s.Whi = w1hi; s.Wlo = w1lo; s.Uhi = u1hi; s.Ulo = u1lo;
        s.bias = b1; s.C = c1;
        s.Ohi = h1hi + cur * SLOT;  s.Olo = h1lo + cur * SLOT;
        s.seqlen = nullptr; s.hfinal = nullptr;
        s.nact = nact;
        s.t = t; s.first = (t == 0) ? 1 : 0;
        return s;
    };
    auto mkL2 = [&](int t) {
        StepArgs s;
        const int prev = t & 1, cur = (t + 1) & 1;
        s.Xhi = h1hi + cur * SLOT;  s.Xlo = h1lo + cur * SLOT;   // L1 output of step t
        s.xstride = (unsigned long long)HDIM;
        s.Kx = HDIM;
        s.Hhi = h2hi + prev * SLOT;  s.Hlo = h2lo + prev * SLOT;
        s.Whi = w2hi; s.Wlo = w2lo; s.Uhi = u2hi; s.Ulo = u2lo;
        s.bias = b2; s.C = c2;
        s.Ohi = h2hi + cur * SLOT;  s.Olo = h2lo + cur * SLOT;
        s.seqlen = slen; s.hfinal = hfin;
        s.nact = nact;
        s.t = t; s.first = (t == 0) ? 1 : 0;
        return s;
    };

    const dim3 grid1(HDIM / BN, B_ROWS / BM, 1);   // (16, 8, 1)
    const dim3 grid2(HDIM / BN, B_ROWS / BM, 2);   // (16, 8, 2)

    {
        StepArgs s = mkL1(0);
        lstm_step<<<grid1, NTH, SMEM_BYTES>>>(s, s);
    }
    for (int k = 1; k < T_STEPS; ++k) {
        StepArgs sA = mkL1(k);
        StepArgs sB = mkL2(k - 1);
        lstm_step<<<grid2, NTH, SMEM_BYTES>>>(sA, sB);
    }
    {
        StepArgs s = mkL2(T_STEPS - 1);
        lstm_step<<<grid1, NTH, SMEM_BYTES>>>(s, s);
    }
    dense_kernel<<<B_ROWS, 256>>>(hfin, perm, Wd, bd, out);
}

// round 7
// speedup vs baseline: 1.2858x; 1.0845x over previous
#include <cuda_runtime.h>
#include <cuda_bf16.h>
#include <cstdint>
#include <math.h>

typedef __nv_bfloat16 bf16;

#define B_ROWS   512
#define T_STEPS  128
#define DIM_IN   256
#define HDIM     1024
#define FOURH    4096

#define BM 64
#define BN 64            // columns per gate per block
#define NTH 512          // 16 warps: 4 (m) x 4 (n)

// smem layout (bytes), 3 stages. Rows: 32 bf16 data in 80B stride.
#define A_STAGE_B (2 * 64 * 80)        // hi+lo planes: 10240
#define B_STAGE_B (2 * 256 * 80)       // hi+lo planes: 40960
#define SM_A_OFF(s) ((s) * A_STAGE_B)
#define SM_B_OFF(s) (3 * A_STAGE_B + (s) * B_STAGE_B)
#define A_PLANE_B (64 * 80)            // 5120
#define B_PLANE_B (256 * 80)           // 20480
#define SMEM_BYTES (3 * A_STAGE_B + 3 * B_STAGE_B)   // 153600

// ---------------- persistent device scratch (sorted row space) ----------------
__device__ bf16  g_h1hi[2][B_ROWS * HDIM];
__device__ bf16  g_h1lo[2][B_ROWS * HDIM];
__device__ bf16  g_h2hi[2][B_ROWS * HDIM];
__device__ bf16  g_h2lo[2][B_ROWS * HDIM];
__device__ float g_c1[(size_t)B_ROWS * HDIM];
__device__ float g_c2[(size_t)B_ROWS * HDIM];
__device__ float g_hfinal[(size_t)B_ROWS * HDIM];
__device__ bf16  g_xhi[(size_t)B_ROWS * T_STEPS * DIM_IN];
__device__ bf16  g_xlo[(size_t)B_ROWS * T_STEPS * DIM_IN];
__device__ int   g_perm[B_ROWS];
__device__ int   g_slen[B_ROWS];
__device__ int   g_nact[T_STEPS];
// transposed split weights: row = gate*1024 + n, K-major
__device__ bf16  g_w1hi[(size_t)FOURH * DIM_IN],  g_w1lo[(size_t)FOURH * DIM_IN];
__device__ bf16  g_u1hi[(size_t)FOURH * HDIM],    g_u1lo[(size_t)FOURH * HDIM];
__device__ bf16  g_w2hi[(size_t)FOURH * HDIM],    g_w2lo[(size_t)FOURH * HDIM];
__device__ bf16  g_u2hi[(size_t)FOURH * HDIM],    g_u2lo[(size_t)FOURH * HDIM];

// ---------------- helpers ----------------
__device__ __forceinline__ uint32_t smem_u32(const void* p) {
    uint32_t a;
    asm("{ .reg .u64 t; cvta.to.shared.u64 t, %1; cvt.u32.u64 %0, t; }" : "=r"(a) : "l"(p));
    return a;
}
__device__ __forceinline__ void cp16(uint32_t s, const void* g) {
    asm volatile("cp.async.cg.shared.global [%0], [%1], 16;" :: "r"(s), "l"(g));
}
__device__ __forceinline__ void cp_commit() { asm volatile("cp.async.commit_group;" ::: "memory"); }
__device__ __forceinline__ void cp_wait1()  { asm volatile("cp.async.wait_group 1;" ::: "memory"); }
__device__ __forceinline__ void cp_wait0()  { asm volatile("cp.async.wait_group 0;" ::: "memory"); }
__device__ __forceinline__ void ldmx4(uint32_t* r, uint32_t a) {
    asm volatile("ldmatrix.sync.aligned.m8n8.x4.shared.b16 {%0,%1,%2,%3}, [%4];"
                 : "=r"(r[0]), "=r"(r[1]), "=r"(r[2]), "=r"(r[3]) : "r"(a));
}
__device__ __forceinline__ void ldmx2(uint32_t* r, uint32_t a) {
    asm volatile("ldmatrix.sync.aligned.m8n8.x2.shared.b16 {%0,%1}, [%2];"
                 : "=r"(r[0]), "=r"(r[1]) : "r"(a));
}
__device__ __forceinline__ void mma_bf16(float* d, const uint32_t* a, const uint32_t* b) {
    asm volatile(
        "mma.sync.aligned.m16n8k16.row.col.f32.bf16.bf16.f32 "
        "{%0,%1,%2,%3}, {%4,%5,%6,%7}, {%8,%9}, {%0,%1,%2,%3};"
        : "+f"(d[0]), "+f"(d[1]), "+f"(d[2]), "+f"(d[3])
        : "r"(a[0]), "r"(a[1]), "r"(a[2]), "r"(a[3]), "r"(b[0]), "r"(b[1]));
}
__device__ __forceinline__ float fsig(float x) { return 1.0f / (1.0f + __expf(-x)); }
__device__ __forceinline__ void split_bf16(float x, bf16& hi, bf16& lo) {
    hi = __float2bfloat16(x);
    lo = __float2bfloat16(x - __bfloat162float(hi));
}

// ---------------- prep kernels ----------------
__global__ void sort_rows(const int* __restrict__ seqlen,
                          int* __restrict__ perm, int* __restrict__ slen,
                          int* __restrict__ nact) {
    __shared__ int keys[B_ROWS];
    const int i = threadIdx.x;
    keys[i] = seqlen[i];
    __syncthreads();
    const int k = keys[i];
    int rank = 0;
    for (int j = 0; j < B_ROWS; ++j) {
        int kj = keys[j];
        rank += (kj > k) || (kj == k && j < i);
    }
    perm[rank] = i;
    slen[rank] = k;
    if (i < T_STEPS) {
        int cnt = 0;
        for (int j = 0; j < B_ROWS; ++j) cnt += (keys[j] >= i + 1);
        nact[i] = cnt;
    }
}

__global__ void split_chars_perm(const float* __restrict__ x,
                                 const int* __restrict__ perm,
                                 bf16* __restrict__ hi, bf16* __restrict__ lo) {
    const int n = B_ROWS * T_STEPS * DIM_IN;
    int i = blockIdx.x * blockDim.x + threadIdx.x;
    if (i >= n) return;
    const int row_elems = T_STEPS * DIM_IN;
    int bs = i / row_elems, d = i - bs * row_elems;
    float v = x[(size_t)perm[bs] * row_elems + d];
    bf16 h, l; split_bf16(v, h, l);
    hi[i] = h; lo[i] = l;
}

__global__ void transpose_split_w(const float* __restrict__ W,
                                  bf16* __restrict__ Whi, bf16* __restrict__ Wlo, int K) {
    __shared__ float tile[32][33];
    int nb = blockIdx.x * 32, kb = blockIdx.y * 32;
    int x = threadIdx.x, y = threadIdx.y;
    #pragma unroll
    for (int yy = y; yy < 32; yy += 8)
        tile[yy][x] = W[(size_t)(kb + yy) * FOURH + nb + x];
    __syncthreads();
    #pragma unroll
    for (int yy = y; yy < 32; yy += 8) {
        float w = tile[x][yy];
        bf16 h, l; split_bf16(w, h, l);
        size_t o = (size_t)(nb + yy) * K + kb + x;
        Whi[o] = h; Wlo[o] = l;
    }
}

// ---------------- per-layer step arguments ----------------
struct StepArgs {
    const bf16* Xhi; const bf16* Xlo;
    unsigned long long xstride;
    int Kx;
    const bf16* Hhi; const bf16* Hlo;
    const bf16* Whi; const bf16* Wlo;
    const bf16* Uhi; const bf16* Ulo;
    const float* bias;
    float* C;
    bf16* Ohi; bf16* Olo;
    const int* seqlen;
    float* hfinal;
    const int* nact;
    int t; int first;
};

// ---------------- fused dual-layer LSTM step (bf16x3 mma.sync, 16 warps) ----------------
__global__ __launch_bounds__(NTH)
void lstm_step(const StepArgs a0, const StepArgs a1)
{
    const StepArgs a = (blockIdx.z == 0) ? a0 : a1;
    const int row0 = blockIdx.y * BM;
    if (row0 >= a.nact[a.t]) return;   // dead rows never influence the output

    extern __shared__ char smemc[];
    const uint32_t sb = smem_u32(smemc);
    const int tid  = threadIdx.x;
    const int lane = tid & 31;
    const int warp = tid >> 5;
    const int wm   = warp >> 2;          // 0..3 -> 16-row slab
    const int wn   = warp & 3;           // 0..3 -> 16-col slab
    const int n0   = blockIdx.x * BN;

    const int arow  = (lane & 7) + ((lane >> 3) & 1) * 8;
    const int koffA = (lane >> 4) * 8;
    const int laneb = lane & 15;
    const int brow  = laneb & 7;
    const int koffB = ((laneb >> 3) & 1) * 8;

    float acc[4][2][4];                  // [gate][ntile][frag]
    #pragma unroll
    for (int g = 0; g < 4; ++g)
        #pragma unroll
        for (int nt = 0; nt < 2; ++nt)
            #pragma unroll
            for (int q = 0; q < 4; ++q) acc[g][nt][q] = 0.f;

    const int c0n = a.Kx >> 5;
    const int nch = a.first ? c0n : (c0n + (HDIM >> 5));

    auto load_chunk = [&](int c, int st) {
        const int seg = (c < c0n) ? 0 : 1;
        const int k0  = ((seg == 0) ? c : (c - c0n)) << 5;
        const bf16* Ah = (seg == 0) ? a.Xhi : a.Hhi;
        const bf16* Al = (seg == 0) ? a.Xlo : a.Hlo;
        const size_t astr = (seg == 0) ? (size_t)a.xstride : (size_t)HDIM;
        const bf16* Bh = (seg == 0) ? a.Whi : a.Uhi;
        const bf16* Bl = (seg == 0) ? a.Wlo : a.Ulo;
        const int   Kb = (seg == 0) ? a.Kx : HDIM;
        // A: 512 cp16 units (2 planes x 64 rows x 4 quads), one per thread
        {
            int u = tid;
            int pl = u >> 8, rem = u & 255, r = rem >> 2, q = rem & 3;
            const bf16* src = (pl ? Al : Ah) + (size_t)(row0 + r) * astr + k0 + q * 8;
            cp16(sb + SM_A_OFF(st) + pl * A_PLANE_B + r * 80 + q * 16, src);
        }
        // B: 2048 cp16 units (2 planes x 256 rows x 4 quads), 4 per thread
        #pragma unroll
        for (int j = 0; j < 4; ++j) {
            int u = j * NTH + tid;
            int pl = u >> 10, rem = u & 1023, r = rem >> 2, q = rem & 3;
            int n4 = ((r >> 6) << 10) + n0 + (r & 63);
            const bf16* src = (pl ? Bl : Bh) + (size_t)n4 * Kb + k0 + q * 8;
            cp16(sb + SM_B_OFF(st) + pl * B_PLANE_B + r * 80 + q * 16, src);
        }
        cp_commit();
    };

    load_chunk(0, 0);
    if (nch > 1) load_chunk(1, 1);

    for (int i = 0; i < nch; ++i) {
        if (i + 1 < nch) cp_wait1(); else cp_wait0();
        __syncthreads();   // single sync: data(i) visible, stage (i+2)%3 free (chunk i-1 done)
        if (i + 2 < nch) load_chunk(i + 2, (i + 2) % 3);

        const int st = i % 3;
        const uint32_t aB = sb + SM_A_OFF(st);
        const uint32_t bB = sb + SM_B_OFF(st);

        #pragma unroll
        for (int ks = 0; ks < 2; ++ks) {
            uint32_t ah[4], al[4];
            uint32_t aa = aB + (uint32_t)((wm * 16 + arow) * 80 + (ks * 16 + koffA) * 2);
            ldmx4(ah, aa);
            ldmx4(al, aa + A_PLANE_B);
            #pragma unroll
            for (int g = 0; g < 4; ++g) {
                #pragma unroll
                for (int nt = 0; nt < 2; ++nt) {
                    uint32_t ba = bB + (uint32_t)((g * 64 + wn * 16 + nt * 8 + brow) * 80
                                                  + (ks * 16 + koffB) * 2);
                    uint32_t bh[2], bl[2];
                    ldmx2(bh, ba);
                    ldmx2(bl, ba + B_PLANE_B);
                    mma_bf16(acc[g][nt], ah, bh);
                    mma_bf16(acc[g][nt], ah, bl);
                    mma_bf16(acc[g][nt], al, bh);
                }
            }
        }
    }

    // ---- fused LSTM cell epilogue ----
    #pragma unroll
    for (int half = 0; half < 2; ++half) {
        const int r = row0 + wm * 16 + half * 8 + (lane >> 2);
        const int slen = a.seqlen ? a.seqlen[r] : 0;
        #pragma unroll
        for (int nt = 0; nt < 2; ++nt) {
            const int c = n0 + wn * 16 + nt * 8 + (lane & 3) * 2;
            float2 cold = make_float2(0.f, 0.f);
            if (!a.first)
                cold = *reinterpret_cast<const float2*>(a.C + (size_t)r * HDIM + c);
            float cn[2], hn[2];
            #pragma unroll
            for (int j = 0; j < 2; ++j) {
                const int q = half * 2 + j;
                float zi = acc[0][nt][q] + a.bias[c + j];
                float zf = acc[1][nt][q] + a.bias[HDIM + c + j];
                float zg = acc[2][nt][q] + a.bias[2 * HDIM + c + j];
                float zo = acc[3][nt][q] + a.bias[3 * HDIM + c + j];
                float ig = fsig(zi), fg = fsig(zf);
                float gg = tanhf(zg), og = fsig(zo);
                float co = (j == 0) ? cold.x : cold.y;
                cn[j] = fmaf(fg, co, ig * gg);
                hn[j] = og * tanhf(cn[j]);
            }
            *reinterpret_cast<float2*>(a.C + (size_t)r * HDIM + c) = make_float2(cn[0], cn[1]);
            bf16 h0, l0, h1, l1;
            split_bf16(hn[0], h0, l0);
            split_bf16(hn[1], h1, l1);
            *reinterpret_cast<__nv_bfloat162*>(a.Ohi + (size_t)r * HDIM + c) =
                __nv_bfloat162(h0, h1);
            *reinterpret_cast<__nv_bfloat162*>(a.Olo + (size_t)r * HDIM + c) =
                __nv_bfloat162(l0, l1);
            if (a.hfinal && slen - 1 == a.t)
                *reinterpret_cast<float2*>(a.hfinal + (size_t)r * HDIM + c) =
                    make_float2(hn[0], hn[1]);
        }
    }
}

// ---------------- final dense(1024->3) + relu (sorted -> original order) ----------------
__global__ void dense_kernel(const float* __restrict__ hfinal,
                             const int* __restrict__ perm,
                             const float* __restrict__ Wd,
                             const float* __restrict__ bd,
                             float* __restrict__ out)
{
    const int bs = blockIdx.x;
    const float* h = hfinal + (size_t)bs * HDIM;

    float s0 = 0.f, s1 = 0.f, s2 = 0.f;
    for (int k = threadIdx.x; k < HDIM; k += blockDim.x) {
        float hv = h[k];
        s0 = fmaf(hv, Wd[k * 3 + 0], s0);
        s1 = fmaf(hv, Wd[k * 3 + 1], s1);
        s2 = fmaf(hv, Wd[k * 3 + 2], s2);
    }
    #pragma unroll
    for (int o = 16; o > 0; o >>= 1) {
        s0 += __shfl_down_sync(0xffffffffu, s0, o);
        s1 += __shfl_down_sync(0xffffffffu, s1, o);
        s2 += __shfl_down_sync(0xffffffffu, s2, o);
    }
    __shared__ float red[8][3];
    const int wid = threadIdx.x >> 5, lane = threadIdx.x & 31;
    if (lane == 0) { red[wid][0] = s0; red[wid][1] = s1; red[wid][2] = s2; }
    __syncthreads();
    if (threadIdx.x == 0) {
        float r0 = 0.f, r1 = 0.f, r2 = 0.f;
        const int nw = blockDim.x >> 5;
        for (int w = 0; w < nw; ++w) { r0 += red[w][0]; r1 += red[w][1]; r2 += red[w][2]; }
        const int b = perm[bs];
        out[b * 3 + 0] = fmaxf(r0 + bd[0], 0.f);
        out[b * 3 + 1] = fmaxf(r1 + bd[1], 0.f);
        out[b * 3 + 2] = fmaxf(r2 + bd[2], 0.f);
    }
}

extern "C" void kernel_launch(void* const* d_in, const int* in_sizes, int n_in,
                              void* d_out, int out_size) {
    const float* chars  = (const float*)d_in[0];
    const int*   seqlen = (const int*)  d_in[1];
    const float* W1 = (const float*)d_in[2];
    const float* U1 = (const float*)d_in[3];
    const float* b1 = (const float*)d_in[4];
    const float* W2 = (const float*)d_in[5];
    const float* U2 = (const float*)d_in[6];
    const float* b2 = (const float*)d_in[7];
    const float* Wd = (const float*)d_in[8];
    const float* bd = (const float*)d_in[9];
    float* out = (float*)d_out;

    bf16 *h1hi, *h1lo, *h2hi, *h2lo, *xhi, *xlo;
    bf16 *w1hi, *w1lo, *u1hi, *u1lo, *w2hi, *w2lo, *u2hi, *u2lo;
    float *c1, *c2, *hfin;
    int *perm, *slen, *nact;
    cudaGetSymbolAddress((void**)&h1hi, g_h1hi);
    cudaGetSymbolAddress((void**)&h1lo, g_h1lo);
    cudaGetSymbolAddress((void**)&h2hi, g_h2hi);
    cudaGetSymbolAddress((void**)&h2lo, g_h2lo);
    cudaGetSymbolAddress((void**)&c1,   g_c1);
    cudaGetSymbolAddress((void**)&c2,   g_c2);
    cudaGetSymbolAddress((void**)&hfin, g_hfinal);
    cudaGetSymbolAddress((void**)&xhi,  g_xhi);
    cudaGetSymbolAddress((void**)&xlo,  g_xlo);
    cudaGetSymbolAddress((void**)&perm, g_perm);
    cudaGetSymbolAddress((void**)&slen, g_slen);
    cudaGetSymbolAddress((void**)&nact, g_nact);
    cudaGetSymbolAddress((void**)&w1hi, g_w1hi);
    cudaGetSymbolAddress((void**)&w1lo, g_w1lo);
    cudaGetSymbolAddress((void**)&u1hi, g_u1hi);
    cudaGetSymbolAddress((void**)&u1lo, g_u1lo);
    cudaGetSymbolAddress((void**)&w2hi, g_w2hi);
    cudaGetSymbolAddress((void**)&w2lo, g_w2lo);
    cudaGetSymbolAddress((void**)&u2hi, g_u2hi);
    cudaGetSymbolAddress((void**)&u2lo, g_u2lo);

    cudaFuncSetAttribute(lstm_step,
                         cudaFuncAttributeMaxDynamicSharedMemorySize, SMEM_BYTES);

    sort_rows<<<1, B_ROWS>>>(seqlen, perm, slen, nact);
    const int nx = B_ROWS * T_STEPS * DIM_IN;
    split_chars_perm<<<(nx + 255) / 256, 256>>>(chars, perm, xhi, xlo);
    const dim3 tb(32, 8);
    transpose_split_w<<<dim3(FOURH / 32, DIM_IN / 32), tb>>>(W1, w1hi, w1lo, DIM_IN);
    transpose_split_w<<<dim3(FOURH / 32, HDIM  / 32), tb>>>(U1, u1hi, u1lo, HDIM);
    transpose_split_w<<<dim3(FOURH / 32, HDIM  / 32), tb>>>(W2, w2hi, w2lo, HDIM);
    transpose_split_w<<<dim3(FOURH / 32, HDIM  / 32), tb>>>(U2, u2hi, u2lo, HDIM);

    const size_t SLOT = (size_t)B_ROWS * HDIM;

    auto mkL1 = [&](int t) {
        StepArgs s;
        const int prev = t & 1, cur = (t + 1) & 1;
        s.Xhi = xhi + (size_t)t * DIM_IN;  s.Xlo = xlo + (size_t)t * DIM_IN;
        s.xstride = (unsigned long long)(T_STEPS * DIM_IN);
        s.Kx = DIM_IN;
        s.Hhi = h1hi + prev * SLOT;  s.Hlo = h1lo + prev * SLOT;
        s.Whi = w1hi; s.Wlo = w1lo; s.Uhi = u1hi; s.Ulo = u1lo;
        s.bias = b1; s.C = c1;
        s.Ohi = h1hi + cur * SLOT;  s.Olo = h1lo + cur * SLOT;
        s.seqlen = nullptr; s.hfinal = nullptr;
        s.nact = nact;
        s.t = t; s.first = (t == 0) ? 1 : 0;
        return s;
    };
    auto mkL2 = [&](int t) {
        StepArgs s;
        const int prev = t & 1, cur = (t + 1) & 1;
        s.Xhi = h1hi + cur * SLOT;  s.Xlo = h1lo + cur * SLOT;
        s.xstride = (unsigned long long)HDIM;
        s.Kx = HDIM;
        s.Hhi = h2hi + prev * SLOT;  s.Hlo = h2lo + prev * SLOT;
        s.Whi = w2hi; s.Wlo = w2lo; s.Uhi = u2hi; s.Ulo = u2lo;
        s.bias = b2; s.C = c2;
        s.Ohi = h2hi + cur * SLOT;  s.Olo = h2lo + cur * SLOT;
        s.seqlen = slen; s.hfinal = hfin;
        s.nact = nact;
        s.t = t; s.first = (t == 0) ? 1 : 0;
        return s;
    };

    const dim3 grid1(HDIM / BN, B_ROWS / BM, 1);   // (16, 8, 1)
    const dim3 grid2(HDIM / BN, B_ROWS / BM, 2);   // (16, 8, 2)

    {
        StepArgs s = mkL1(0);
        lstm_step<<<grid1, NTH, SMEM_BYTES>>>(s, s);
    }
    for (int k = 1; k < T_STEPS; ++k) {
        StepArgs sA = mkL1(k);
        StepArgs sB = mkL2(k - 1);
        lstm_step<<<grid2, NTH, SMEM_BYTES>>>(sA, sB);
    }
    {
        StepArgs s = mkL2(T_STEPS - 1);
        lstm_step<<<grid1, NTH, SMEM_BYTES>>>(s, s);
    }
    dense_kernel<<<B_ROWS, 256>>>(hfin, perm, Wd, bd, out);
}

// round 8
// speedup vs baseline: 1.9614x; 1.5255x over previous
#include <cuda_runtime.h>
#include <cuda_bf16.h>
#include <cstdint>
#include <math.h>

typedef __nv_bfloat16 bf16;

#define B_ROWS   512
#define T_STEPS  128
#define DIM_IN   256
#define HDIM     1024
#define FOURH    4096

#define BM 64
#define BN 64            // columns per gate per block
#define NTH 512          // 16 warps: 4 (m) x 4 (n)

// Tile images (gmem layout == smem layout):
// A tile: [2 planes][64 rows][80 B]  = 10240 B
// B tile: [2 planes][256 rows][80 B] = 40960 B  (row = gate*64 + n_local)
#define A_TILE_B  10240
#define B_TILE_B  40960
#define A_PLANE_B 5120
#define B_PLANE_B 20480
#define STAGE_B   (A_TILE_B + B_TILE_B)          // 51200

// smem: [0..24) 3 mbarriers, stages at 1024
#define SM_A_OFF(s) (1024 + (s) * STAGE_B)
#define SM_B_OFF(s) (SM_A_OFF(s) + A_TILE_B)
#define SMEM_BYTES  (1024 + 3 * STAGE_B)         // 154624

// ---------------- persistent device scratch (sorted row space) ----------------
// tiled x: [t][rowblk(8)][kc(8)] tiles
__device__ __align__(128) char g_xt[(size_t)T_STEPS * 8 * 8 * A_TILE_B];
// tiled h (2 slots each): [rowblk(8)][kc(32)] tiles
__device__ __align__(128) char g_h1t[2][(size_t)8 * 32 * A_TILE_B];
__device__ __align__(128) char g_h2t[2][(size_t)8 * 32 * A_TILE_B];
// tiled weights: [nblk(16)][kc(K/32)] tiles
__device__ __align__(128) char g_w1t[(size_t)16 * 8  * B_TILE_B];
__device__ __align__(128) char g_u1t[(size_t)16 * 32 * B_TILE_B];
__device__ __align__(128) char g_w2t[(size_t)16 * 32 * B_TILE_B];
__device__ __align__(128) char g_u2t[(size_t)16 * 32 * B_TILE_B];
__device__ float g_c1[(size_t)B_ROWS * HDIM];
__device__ float g_c2[(size_t)B_ROWS * HDIM];
__device__ float g_hfinal[(size_t)B_ROWS * HDIM];
__device__ int   g_perm[B_ROWS];
__device__ int   g_slen[B_ROWS];
__device__ int   g_nact[T_STEPS];

// ---------------- helpers ----------------
__device__ __forceinline__ uint32_t smem_u32(const void* p) {
    uint32_t a;
    asm("{ .reg .u64 t; cvta.to.shared.u64 t, %1; cvt.u32.u64 %0, t; }" : "=r"(a) : "l"(p));
    return a;
}
__device__ __forceinline__ void mbar_init(uint32_t a, uint32_t cnt) {
    asm volatile("mbarrier.init.shared.b64 [%0], %1;" :: "r"(a), "r"(cnt) : "memory");
}
__device__ __forceinline__ void mbar_expect(uint32_t a, uint32_t bytes) {
    asm volatile("mbarrier.arrive.expect_tx.shared.b64 _, [%0], %1;"
                 :: "r"(a), "r"(bytes) : "memory");
}
__device__ __forceinline__ void mbar_wait(uint32_t a, uint32_t parity) {
    asm volatile(
        "{\n\t.reg .pred P;\n\t"
        "WL_%=:\n\t"
        "mbarrier.try_wait.parity.acquire.cta.shared::cta.b64 P, [%0], %1, 0x989680;\n\t"
        "@P bra.uni WD_%=;\n\t"
        "bra.uni WL_%=;\n\t"
        "WD_%=:\n\t}"
        :: "r"(a), "r"(parity) : "memory");
}
__device__ __forceinline__ void bulk_g2s(uint32_t dst, const void* src,
                                         uint32_t bytes, uint32_t mbar) {
    asm volatile(
        "cp.async.bulk.shared::cluster.global.mbarrier::complete_tx::bytes "
        "[%0], [%1], %2, [%3];"
        :: "r"(dst), "l"(src), "r"(bytes), "r"(mbar) : "memory");
}
__device__ __forceinline__ void ldmx4(uint32_t* r, uint32_t a) {
    asm volatile("ldmatrix.sync.aligned.m8n8.x4.shared.b16 {%0,%1,%2,%3}, [%4];"
                 : "=r"(r[0]), "=r"(r[1]), "=r"(r[2]), "=r"(r[3]) : "r"(a));
}
__device__ __forceinline__ void ldmx2(uint32_t* r, uint32_t a) {
    asm volatile("ldmatrix.sync.aligned.m8n8.x2.shared.b16 {%0,%1}, [%2];"
                 : "=r"(r[0]), "=r"(r[1]) : "r"(a));
}
__device__ __forceinline__ void mma_bf16(float* d, const uint32_t* a, const uint32_t* b) {
    asm volatile(
        "mma.sync.aligned.m16n8k16.row.col.f32.bf16.bf16.f32 "
        "{%0,%1,%2,%3}, {%4,%5,%6,%7}, {%8,%9}, {%0,%1,%2,%3};"
        : "+f"(d[0]), "+f"(d[1]), "+f"(d[2]), "+f"(d[3])
        : "r"(a[0]), "r"(a[1]), "r"(a[2]), "r"(a[3]), "r"(b[0]), "r"(b[1]));
}
__device__ __forceinline__ float fsig(float x) { return 1.0f / (1.0f + __expf(-x)); }
__device__ __forceinline__ void split_bf16(float x, bf16& hi, bf16& lo) {
    hi = __float2bfloat16(x);
    lo = __float2bfloat16(x - __bfloat162float(hi));
}

// ---------------- prep kernels ----------------
__global__ void sort_rows(const int* __restrict__ seqlen,
                          int* __restrict__ perm, int* __restrict__ slen,
                          int* __restrict__ nact) {
    __shared__ int keys[B_ROWS];
    const int i = threadIdx.x;
    keys[i] = seqlen[i];
    __syncthreads();
    const int k = keys[i];
    int rank = 0;
    for (int j = 0; j < B_ROWS; ++j) {
        int kj = keys[j];
        rank += (kj > k) || (kj == k && j < i);
    }
    perm[rank] = i;
    slen[rank] = k;
    if (i < T_STEPS) {
        int cnt = 0;
        for (int j = 0; j < B_ROWS; ++j) cnt += (keys[j] >= i + 1);
        nact[i] = cnt;
    }
}

// chars -> sorted rows, split, tiled A-images
__global__ void split_chars_tiled(const float* __restrict__ x,
                                  const int* __restrict__ perm,
                                  char* __restrict__ xt) {
    const int n = B_ROWS * T_STEPS * DIM_IN;
    int i = blockIdx.x * blockDim.x + threadIdx.x;
    if (i >= n) return;
    const int row_elems = T_STEPS * DIM_IN;
    int bs = i / row_elems, d = i - bs * row_elems;
    int t = d >> 8, k = d & 255;
    float v = x[(size_t)perm[bs] * row_elems + d];
    bf16 h, l; split_bf16(v, h, l);
    size_t base = (((size_t)t * 8 + (bs >> 6)) * 8 + (k >> 5)) * A_TILE_B
                + (size_t)(bs & 63) * 80 + (k & 31) * 2;
    *reinterpret_cast<bf16*>(xt + base)             = h;
    *reinterpret_cast<bf16*>(xt + base + A_PLANE_B) = l;
}

// W[K][4096] fp32 -> tiled split B-images
__global__ void transpose_split_w_tiled(const float* __restrict__ W,
                                        char* __restrict__ Wt, int K) {
    __shared__ float tile[32][33];
    int nb = blockIdx.x * 32, kb = blockIdx.y * 32;
    int x = threadIdx.x, y = threadIdx.y;
    #pragma unroll
    for (int yy = y; yy < 32; yy += 8)
        tile[yy][x] = W[(size_t)(kb + yy) * FOURH + nb + x];
    __syncthreads();
    const int KC = K >> 5;
    #pragma unroll
    for (int yy = y; yy < 32; yy += 8) {
        float w = tile[x][yy];
        bf16 h, l; split_bf16(w, h, l);
        int n4 = nb + yy, k = kb + x;
        int g = n4 >> 10, rr = n4 & 1023;
        int nblk = rr >> 6, nl = rr & 63;
        int kc = k >> 5, kl = k & 31;
        size_t base = ((size_t)(nblk * KC + kc)) * B_TILE_B
                    + (size_t)(g * 64 + nl) * 80 + kl * 2;
        *reinterpret_cast<bf16*>(Wt + base)             = h;
        *reinterpret_cast<bf16*>(Wt + base + B_PLANE_B) = l;
    }
}

// ---------------- per-layer step arguments ----------------
struct StepArgs {
    const char* Ax;      // tiled X (A seg0), layout [rowblk][KC0]
    const char* Hx;      // tiled Hprev (A seg1), layout [rowblk][32]
    const char* Bw;      // tiled W (B seg0), layout [nblk][KC0]
    const char* Bu;      // tiled U (B seg1), layout [nblk][32]
    int KC0;             // k-chunks in seg0 (8 or 32)
    const float* bias;
    float* C;
    char* Ot;            // tiled h output, layout [rowblk][32]
    const int* seqlen;
    float* hfinal;
    const int* nact;
    int t; int first;
};

// ---------------- fused dual-layer LSTM step (bf16x3 mma.sync + bulk-copy) --------
__global__ __launch_bounds__(NTH)
void lstm_step(const StepArgs a0, const StepArgs a1)
{
    const StepArgs a = (blockIdx.z == 0) ? a0 : a1;
    const int rowblk = blockIdx.y;
    const int row0 = rowblk * BM;
    if (row0 >= a.nact[a.t]) return;   // dead rows never influence the output

    extern __shared__ char smemc[];
    const uint32_t sb = smem_u32(smemc);
    const int tid  = threadIdx.x;
    const int lane = tid & 31;
    const int warp = tid >> 5;
    const int wm   = warp >> 2;          // 0..3 -> 16-row slab
    const int wn   = warp & 3;           // 0..3 -> 16-col slab
    const int nblk = blockIdx.x;
    const int n0   = nblk * BN;

    const int arow  = (lane & 7) + ((lane >> 3) & 1) * 8;
    const int koffA = (lane >> 4) * 8;
    const int laneb = lane & 15;
    const int brow  = laneb & 7;
    const int koffB = ((laneb >> 3) & 1) * 8;

    float acc[4][2][4];
    #pragma unroll
    for (int g = 0; g < 4; ++g)
        #pragma unroll
        for (int nt = 0; nt < 2; ++nt)
            #pragma unroll
            for (int q = 0; q < 4; ++q) acc[g][nt][q] = 0.f;

    const int KC0i = a.KC0;
    const int nch = a.first ? KC0i : (KC0i + 32);

    auto issue = [&](int c) {
        const int st = c % 3;
        const uint32_t mb = sb + st * 8;
        const int seg = (c < KC0i) ? 0 : 1;
        const int kc  = seg ? (c - KC0i) : c;
        const char* As = seg ? (a.Hx + ((size_t)(rowblk * 32 + kc)) * A_TILE_B)
                             : (a.Ax + ((size_t)(rowblk * KC0i + kc)) * A_TILE_B);
        const char* Bs = seg ? (a.Bu + ((size_t)(nblk * 32 + kc)) * B_TILE_B)
                             : (a.Bw + ((size_t)(nblk * KC0i + kc)) * B_TILE_B);
        mbar_expect(mb, STAGE_B);
        bulk_g2s(sb + SM_A_OFF(st), As, A_TILE_B, mb);
        bulk_g2s(sb + SM_B_OFF(st), Bs, B_TILE_B, mb);
    };

    if (tid == 0) {
        #pragma unroll
        for (int s = 0; s < 3; ++s) mbar_init(sb + s * 8, 1);
        asm volatile("fence.proxy.async.shared::cta;" ::: "memory");
        issue(0);
        if (nch > 1) issue(1);
    }
    __syncthreads();

    for (int i = 0; i < nch; ++i) {
        mbar_wait(sb + (i % 3) * 8, (uint32_t)((i / 3) & 1));
        __syncthreads();   // all warps done with stage (i+2)%3 (iteration i-1)
        if (tid == 0 && i + 2 < nch) issue(i + 2);

        const int st = i % 3;
        const uint32_t aB = sb + SM_A_OFF(st);
        const uint32_t bB = sb + SM_B_OFF(st);

        #pragma unroll
        for (int ks = 0; ks < 2; ++ks) {
            uint32_t ah[4], al[4];
            uint32_t aa = aB + (uint32_t)((wm * 16 + arow) * 80 + (ks * 16 + koffA) * 2);
            ldmx4(ah, aa);
            ldmx4(al, aa + A_PLANE_B);
            #pragma unroll
            for (int g = 0; g < 4; ++g) {
                #pragma unroll
                for (int nt = 0; nt < 2; ++nt) {
                    uint32_t ba = bB + (uint32_t)((g * 64 + wn * 16 + nt * 8 + brow) * 80
                                                  + (ks * 16 + koffB) * 2);
                    uint32_t bh[2], bl[2];
                    ldmx2(bh, ba);
                    ldmx2(bl, ba + B_PLANE_B);
                    mma_bf16(acc[g][nt], ah, bh);
                    mma_bf16(acc[g][nt], ah, bl);
                    mma_bf16(acc[g][nt], al, bh);
                }
            }
        }
    }

    // ---- fused LSTM cell epilogue (h written in tiled A-image layout) ----
    #pragma unroll
    for (int half = 0; half < 2; ++half) {
        const int r = row0 + wm * 16 + half * 8 + (lane >> 2);
        const int slen = a.seqlen ? a.seqlen[r] : 0;
        #pragma unroll
        for (int nt = 0; nt < 2; ++nt) {
            const int c = n0 + wn * 16 + nt * 8 + (lane & 3) * 2;
            float2 cold = make_float2(0.f, 0.f);
            if (!a.first)
                cold = *reinterpret_cast<const float2*>(a.C + (size_t)r * HDIM + c);
            float cn[2], hn[2];
            #pragma unroll
            for (int j = 0; j < 2; ++j) {
                const int q = half * 2 + j;
                float zi = acc[0][nt][q] + a.bias[c + j];
                float zf = acc[1][nt][q] + a.bias[HDIM + c + j];
                float zg = acc[2][nt][q] + a.bias[2 * HDIM + c + j];
                float zo = acc[3][nt][q] + a.bias[3 * HDIM + c + j];
                float ig = fsig(zi), fg = fsig(zf);
                float gg = tanhf(zg), og = fsig(zo);
                float co = (j == 0) ? cold.x : cold.y;
                cn[j] = fmaf(fg, co, ig * gg);
                hn[j] = og * tanhf(cn[j]);
            }
            *reinterpret_cast<float2*>(a.C + (size_t)r * HDIM + c) = make_float2(cn[0], cn[1]);
            bf16 h0, l0, h1, l1;
            split_bf16(hn[0], h0, l0);
            split_bf16(hn[1], h1, l1);
            size_t toff = ((size_t)((r >> 6) * 32 + (c >> 5))) * A_TILE_B
                        + (size_t)(r & 63) * 80 + (c & 31) * 2;
            *reinterpret_cast<__nv_bfloat162*>(a.Ot + toff) = __nv_bfloat162(h0, h1);
            *reinterpret_cast<__nv_bfloat162*>(a.Ot + toff + A_PLANE_B) = __nv_bfloat162(l0, l1);
            if (a.hfinal && slen - 1 == a.t)
                *reinterpret_cast<float2*>(a.hfinal + (size_t)r * HDIM + c) =
                    make_float2(hn[0], hn[1]);
        }
    }
}

// ---------------- final dense(1024->3) + relu (sorted -> original order) ----------------
__global__ void dense_kernel(const float* __restrict__ hfinal,
                             const int* __restrict__ perm,
                             const float* __restrict__ Wd,
                             const float* __restrict__ bd,
                             float* __restrict__ out)
{
    const int bs = blockIdx.x;
    const float* h = hfinal + (size_t)bs * HDIM;

    float s0 = 0.f, s1 = 0.f, s2 = 0.f;
    for (int k = threadIdx.x; k < HDIM; k += blockDim.x) {
        float hv = h[k];
        s0 = fmaf(hv, Wd[k * 3 + 0], s0);
        s1 = fmaf(hv, Wd[k * 3 + 1], s1);
        s2 = fmaf(hv, Wd[k * 3 + 2], s2);
    }
    #pragma unroll
    for (int o = 16; o > 0; o >>= 1) {
        s0 += __shfl_down_sync(0xffffffffu, s0, o);
        s1 += __shfl_down_sync(0xffffffffu, s1, o);
        s2 += __shfl_down_sync(0xffffffffu, s2, o);
    }
    __shared__ float red[8][3];
    const int wid = threadIdx.x >> 5, lane = threadIdx.x & 31;
    if (lane == 0) { red[wid][0] = s0; red[wid][1] = s1; red[wid][2] = s2; }
    __syncthreads();
    if (threadIdx.x == 0) {
        float r0 = 0.f, r1 = 0.f, r2 = 0.f;
        const int nw = blockDim.x >> 5;
        for (int w = 0; w < nw; ++w) { r0 += red[w][0]; r1 += red[w][1]; r2 += red[w][2]; }
        const int b = perm[bs];
        out[b * 3 + 0] = fmaxf(r0 + bd[0], 0.f);
        out[b * 3 + 1] = fmaxf(r1 + bd[1], 0.f);
        out[b * 3 + 2] = fmaxf(r2 + bd[2], 0.f);
    }
}

extern "C" void kernel_launch(void* const* d_in, const int* in_sizes, int n_in,
                              void* d_out, int out_size) {
    const float* chars  = (const float*)d_in[0];
    const int*   seqlen = (const int*)  d_in[1];
    const float* W1 = (const float*)d_in[2];
    const float* U1 = (const float*)d_in[3];
    const float* b1 = (const float*)d_in[4];
    const float* W2 = (const float*)d_in[5];
    const float* U2 = (const float*)d_in[6];
    const float* b2 = (const float*)d_in[7];
    const float* Wd = (const float*)d_in[8];
    const float* bd = (const float*)d_in[9];
    float* out = (float*)d_out;

    char *xt, *h1t, *h2t, *w1t, *u1t, *w2t, *u2t;
    float *c1, *c2, *hfin;
    int *perm, *slen, *nact;
    cudaGetSymbolAddress((void**)&xt,   g_xt);
    cudaGetSymbolAddress((void**)&h1t,  g_h1t);
    cudaGetSymbolAddress((void**)&h2t,  g_h2t);
    cudaGetSymbolAddress((void**)&w1t,  g_w1t);
    cudaGetSymbolAddress((void**)&u1t,  g_u1t);
    cudaGetSymbolAddress((void**)&w2t,  g_w2t);
    cudaGetSymbolAddress((void**)&u2t,  g_u2t);
    cudaGetSymbolAddress((void**)&c1,   g_c1);
    cudaGetSymbolAddress((void**)&c2,   g_c2);
    cudaGetSymbolAddress((void**)&hfin, g_hfinal);
    cudaGetSymbolAddress((void**)&perm, g_perm);
    cudaGetSymbolAddress((void**)&slen, g_slen);
    cudaGetSymbolAddress((void**)&nact, g_nact);

    cudaFuncSetAttribute(lstm_step,
                         cudaFuncAttributeMaxDynamicSharedMemorySize, SMEM_BYTES);

    const size_t HSLOT = (size_t)8 * 32 * A_TILE_B;

    sort_rows<<<1, B_ROWS>>>(seqlen, perm, slen, nact);
    const int nx = B_ROWS * T_STEPS * DIM_IN;
    split_chars_tiled<<<(nx + 255) / 256, 256>>>(chars, perm, xt);
    const dim3 tb(32, 8);
    transpose_split_w_tiled<<<dim3(FOURH / 32, DIM_IN / 32), tb>>>(W1, w1t, DIM_IN);
    transpose_split_w_tiled<<<dim3(FOURH / 32, HDIM  / 32), tb>>>(U1, u1t, HDIM);
    transpose_split_w_tiled<<<dim3(FOURH / 32, HDIM  / 32), tb>>>(W2, w2t, HDIM);
    transpose_split_w_tiled<<<dim3(FOURH / 32, HDIM  / 32), tb>>>(U2, u2t, HDIM);

    auto mkL1 = [&](int t) {
        StepArgs s;
        const int prev = t & 1, cur = (t + 1) & 1;
        s.Ax = xt + (size_t)t * 8 * 8 * A_TILE_B;
        s.Hx = h1t + prev * HSLOT;
        s.Bw = w1t; s.Bu = u1t;
        s.KC0 = DIM_IN / 32;           // 8
        s.bias = b1; s.C = c1;
        s.Ot = h1t + cur * HSLOT;
        s.seqlen = nullptr; s.hfinal = nullptr;
        s.nact = nact;
        s.t = t; s.first = (t == 0) ? 1 : 0;
        return s;
    };
    auto mkL2 = [&](int t) {
        StepArgs s;
        const int prev = t & 1, cur = (t + 1) & 1;
        s.Ax = h1t + cur * HSLOT;      // L1 output of step t
        s.Hx = h2t + prev * HSLOT;
        s.Bw = w2t; s.Bu = u2t;
        s.KC0 = HDIM / 32;             // 32
        s.bias = b2; s.C = c2;
        s.Ot = h2t + cur * HSLOT;
        s.seqlen = slen; s.hfinal = hfin;
        s.nact = nact;
        s.t = t; s.first = (t == 0) ? 1 : 0;
        return s;
    };

    const dim3 grid1(HDIM / BN, B_ROWS / BM, 1);   // (16, 8, 1)
    const dim3 grid2(HDIM / BN, B_ROWS / BM, 2);   // (16, 8, 2)

    {
        StepArgs s = mkL1(0);
        lstm_step<<<grid1, NTH, SMEM_BYTES>>>(s, s);
    }
    for (int k = 1; k < T_STEPS; ++k) {
        StepArgs sA = mkL1(k);
        StepArgs sB = mkL2(k - 1);
        lstm_step<<<grid2, NTH, SMEM_BYTES>>>(sA, sB);
    }
    {
        StepArgs s = mkL2(T_STEPS - 1);
        lstm_step<<<grid1, NTH, SMEM_BYTES>>>(s, s);
    }
    dense_kernel<<<B_ROWS, 256>>>(hfin, perm, Wd, bd, out);
}